// round 1
// baseline (speedup 1.0000x reference)
#include <cuda_runtime.h>
#include <math.h>

#define LL   12
#define BB   4
#define CC   768
#define HHH  16
#define WWW  16
#define NN   30000
#define DD   128
#define PEK  192
#define HWK  256
#define NBLK_SEL 938   // ceil(30000/32)

// ---------------- scratch (no allocations allowed) ----------------
__device__ float g_cwT [LL*CC*DD];        // conv_w transposed: [l][c][d]
__device__ float g_feat[LL*HWK*BB*DD];    // [l][site][b][d]
__device__ float g_gb  [LL*BB*DD];        // [l][b][d]
__device__ float g_selL[NN*LL];           // softmax layer weights
__device__ float g_px  [NN];
__device__ float g_py  [NN];
__device__ float g_ss  [NN];
__device__ float g_part[2*NBLK_SEL];      // per-block (entropy_sum, scale_sq_sum)

__device__ __forceinline__ float gelu_exact(float x) {
    return 0.5f * x * (1.0f + erff(x * 0.7071067811865476f));
}

// ---------------- conv_w transpose: [l][d][c] -> [l][c][d] ----------------
__global__ void transpose_cw_kernel(const float* __restrict__ cw) {
    __shared__ float t[32][33];
    const int l  = blockIdx.z;
    const int d0 = blockIdx.x * 32;   // over DD (128) -> 4
    const int c0 = blockIdx.y * 32;   // over CC (768) -> 24
    for (int i = threadIdx.y; i < 32; i += 8)
        t[i][threadIdx.x] = cw[((size_t)l*DD + d0 + i)*CC + c0 + threadIdx.x];
    __syncthreads();
    for (int i = threadIdx.y; i < 32; i += 8)
        g_cwT[((size_t)l*CC + c0 + i)*DD + d0 + threadIdx.x] = t[threadIdx.x][i];
}

// ---------------- selector: pe -> 3x MLP -> (space, layer, scale) ----------------
__global__ __launch_bounds__(256) void selector_kernel(
    const float* __restrict__ coords,
    const float* __restrict__ W1all, const float* __restrict__ b1all,
    const float* __restrict__ W2all, const float* __restrict__ b2all,
    const float* __restrict__ W3s,   const float* __restrict__ W3l,
    const float* __restrict__ W3c)
{
    __shared__ float pe[32][PEK+1];
    __shared__ float hb[32][DD+1];
    __shared__ float outs[32][12];
    __shared__ float ent_s[32];
    __shared__ float sq_s[32];

    const int tid = threadIdx.x;
    const int n0  = blockIdx.x * 32;

    // positional encoding
    for (int idx = tid; idx < 32*PEK; idx += 256) {
        int n = idx / PEK, k = idx - n*PEK;
        int c = k >> 6, r = k & 63, f = r & 31;
        int gn = n0 + n;
        float x = (gn < NN) ? coords[gn*3 + c] : 0.0f;
        float freq = exp2f((8.0f/31.0f) * (float)f) * 3.14159265358979323846f;
        float ang = x * freq;
        pe[n][k] = (r < 32) ? sinf(ang) : cosf(ang);
    }
    __syncthreads();

    const int tn = tid >> 5;     // 0..7 : n-subtile
    const int tj = tid & 31;     // 0..31: j-subtile
    const int nb = tn * 4;
    const int jb = tj * 4;

    for (int head = 0; head < 3; head++) {
        const float* w1 = W1all + (size_t)head*PEK*DD;
        const float* w2 = W2all + (size_t)head*DD*DD;

        // ---- layer 1: h = gelu(pe @ W1 + b1)  (32x128 tile; thread = 4n x 4j)
        float acc[4][4];
        #pragma unroll
        for (int i = 0; i < 4; i++)
            #pragma unroll
            for (int j = 0; j < 4; j++) acc[i][j] = 0.0f;

        for (int k = 0; k < PEK; k++) {
            float4 w = *(const float4*)(w1 + (size_t)k*DD + jb);
            float p0 = pe[nb+0][k], p1 = pe[nb+1][k];
            float p2 = pe[nb+2][k], p3 = pe[nb+3][k];
            acc[0][0]+=p0*w.x; acc[0][1]+=p0*w.y; acc[0][2]+=p0*w.z; acc[0][3]+=p0*w.w;
            acc[1][0]+=p1*w.x; acc[1][1]+=p1*w.y; acc[1][2]+=p1*w.z; acc[1][3]+=p1*w.w;
            acc[2][0]+=p2*w.x; acc[2][1]+=p2*w.y; acc[2][2]+=p2*w.z; acc[2][3]+=p2*w.w;
            acc[3][0]+=p3*w.x; acc[3][1]+=p3*w.y; acc[3][2]+=p3*w.z; acc[3][3]+=p3*w.w;
        }
        {
            float4 bv = *(const float4*)(b1all + head*DD + jb);
            float bz[4] = {bv.x, bv.y, bv.z, bv.w};
            #pragma unroll
            for (int i = 0; i < 4; i++)
                #pragma unroll
                for (int j = 0; j < 4; j++)
                    hb[nb+i][jb+j] = gelu_exact(acc[i][j] + bz[j]);
        }
        __syncthreads();

        // ---- layer 2: h = gelu(h @ W2 + b2)
        #pragma unroll
        for (int i = 0; i < 4; i++)
            #pragma unroll
            for (int j = 0; j < 4; j++) acc[i][j] = 0.0f;

        for (int k = 0; k < DD; k++) {
            float4 w = *(const float4*)(w2 + (size_t)k*DD + jb);
            float p0 = hb[nb+0][k], p1 = hb[nb+1][k];
            float p2 = hb[nb+2][k], p3 = hb[nb+3][k];
            acc[0][0]+=p0*w.x; acc[0][1]+=p0*w.y; acc[0][2]+=p0*w.z; acc[0][3]+=p0*w.w;
            acc[1][0]+=p1*w.x; acc[1][1]+=p1*w.y; acc[1][2]+=p1*w.z; acc[1][3]+=p1*w.w;
            acc[2][0]+=p2*w.x; acc[2][1]+=p2*w.y; acc[2][2]+=p2*w.z; acc[2][3]+=p2*w.w;
            acc[3][0]+=p3*w.x; acc[3][1]+=p3*w.y; acc[3][2]+=p3*w.z; acc[3][3]+=p3*w.w;
        }
        __syncthreads();   // all reads of h1 done before overwrite
        {
            float4 bv = *(const float4*)(b2all + head*DD + jb);
            float bz[4] = {bv.x, bv.y, bv.z, bv.w};
            #pragma unroll
            for (int i = 0; i < 4; i++)
                #pragma unroll
                for (int j = 0; j < 4; j++)
                    hb[nb+i][jb+j] = gelu_exact(acc[i][j] + bz[j]);
        }
        __syncthreads();

        // ---- W3 + activation
        if (head == 0) {            // space -> tanh -> pixel coords
            if (tid < 64) {
                int n = tid >> 1, j = tid & 1;
                float a = 0.0f;
                for (int k = 0; k < DD; k++) a += hb[n][k] * W3s[k*2 + j];
                outs[n][j] = tanhf(a);
            }
            __syncthreads();
            if (tid < 32) {
                int gn = n0 + tid;
                if (gn < NN) {
                    g_px[gn] = (outs[tid][0] + 1.0f) * (WWW * 0.5f) - 0.5f;
                    g_py[gn] = (outs[tid][1] + 1.0f) * (HHH * 0.5f) - 0.5f;
                }
            }
            __syncthreads();
        } else if (head == 1) {     // layer -> softmax + entropy
            for (int idx = tid; idx < 32*12; idx += 256) {
                int n = idx / 12, j = idx - n*12;
                float a = 0.0f;
                for (int k = 0; k < DD; k++) a += hb[n][k] * W3l[k*12 + j];
                outs[n][j] = a;
            }
            __syncthreads();
            if (tid < 32) {
                int gn = n0 + tid;
                float m = outs[tid][0];
                #pragma unroll
                for (int l = 1; l < 12; l++) m = fmaxf(m, outs[tid][l]);
                float s = 0.0f, e[12];
                #pragma unroll
                for (int l = 0; l < 12; l++) { e[l] = expf(outs[tid][l] - m); s += e[l]; }
                float inv = 1.0f / s;
                float en = 0.0f;
                #pragma unroll
                for (int l = 0; l < 12; l++) {
                    float p = e[l] * inv;
                    if (gn < NN) g_selL[(size_t)gn*12 + l] = p;
                    en += p * logf(p + 1e-8f);
                }
                ent_s[tid] = (gn < NN) ? en : 0.0f;
            }
            __syncthreads();
        } else {                    // scale -> sigmoid
            if (tid < 32) {
                int gn = n0 + tid;
                float a = 0.0f;
                for (int k = 0; k < DD; k++) a += hb[tid][k] * W3c[k];
                float s = 1.0f / (1.0f + expf(-a));
                if (gn < NN) g_ss[gn] = s;
                sq_s[tid] = (gn < NN) ? (s - 0.5f) * (s - 0.5f) : 0.0f;
            }
            __syncthreads();
        }
    }

    if (tid == 0) {
        float es = 0.0f, qs = 0.0f;
        for (int i = 0; i < 32; i++) { es += ent_s[i]; qs += sq_s[i]; }
        g_part[blockIdx.x*2 + 0] = es;
        g_part[blockIdx.x*2 + 1] = qs;
    }
}

// ---------------- feat GEMM: feat[l][site][b][d] = sum_c local[l,b,c,site]*conv_w[l,d,c] ---------
__global__ __launch_bounds__(256) void feat_kernel(const float* __restrict__ lt) {
    __shared__ float a_s[8][36];
    __shared__ float w_s[8][128];
    const int lb  = blockIdx.y;          // l*4 + b
    const int l   = lb >> 2;
    const int b   = lb & 3;
    const int hw0 = blockIdx.x * 32;
    const int tid = threadIdx.x;
    const int td  = tid & 31;
    const int thw = tid >> 5;            // 0..7

    float acc[4][4];
    #pragma unroll
    for (int i = 0; i < 4; i++)
        #pragma unroll
        for (int j = 0; j < 4; j++) acc[i][j] = 0.0f;

    const float* base = lt + (size_t)lb * CC * HWK;

    for (int c0 = 0; c0 < CC; c0 += 8) {
        {
            int kk = tid >> 5, s = tid & 31;
            a_s[kk][s] = base[(size_t)(c0+kk)*HWK + hw0 + s];
            *(float4*)&w_s[kk][s*4] =
                *(const float4*)&g_cwT[((size_t)l*CC + c0 + kk)*DD + s*4];
        }
        __syncthreads();
        #pragma unroll
        for (int kk = 0; kk < 8; kk++) {
            float4 w = *(float4*)&w_s[kk][td*4];
            #pragma unroll
            for (int i = 0; i < 4; i++) {
                float p = a_s[kk][thw*4 + i];
                acc[i][0] += p*w.x; acc[i][1] += p*w.y;
                acc[i][2] += p*w.z; acc[i][3] += p*w.w;
            }
        }
        __syncthreads();
    }
    #pragma unroll
    for (int i = 0; i < 4; i++) {
        int site = hw0 + thw*4 + i;
        float4 v = make_float4(acc[i][0], acc[i][1], acc[i][2], acc[i][3]);
        *(float4*)&g_feat[(((size_t)l*HWK + site)*BB + b)*DD + td*4] = v;
    }
}

// ---------------- global bottleneck: gb[l][b][d] = dot(global_tokens[l,b,:], glob_w[l,d,:]) ------
__global__ __launch_bounds__(256) void gb_kernel(const float* __restrict__ gt,
                                                 const float* __restrict__ gw) {
    int wid  = (blockIdx.x * 256 + threadIdx.x) >> 5;
    int lane = threadIdx.x & 31;
    if (wid >= LL*BB*DD) return;
    int l = wid / (BB*DD);
    int r = wid - l*(BB*DD);
    int b = r / DD;
    int d = r - b*DD;
    const float* a = gt + (size_t)(l*BB + b)*CC;
    const float* w = gw + (size_t)(l*DD + d)*CC;
    float s = 0.0f;
    for (int c = lane; c < CC; c += 32) s += a[c] * w[c];
    #pragma unroll
    for (int o = 16; o; o >>= 1) s += __shfl_xor_sync(0xffffffffu, s, o);
    if (lane == 0) g_gb[(size_t)(l*BB + b)*DD + d] = s;
}

// ---------------- final: bilinear gather + layer mix + blend + output dot --------------
__global__ __launch_bounds__(256) void final_kernel(const float* __restrict__ ow,
                                                    const float* __restrict__ ob,
                                                    float* __restrict__ out) {
    __shared__ float gb_s[LL*BB*DD];   // 24KB
    __shared__ float sl_s[32][12];
    __shared__ float px_s[32], py_s[32], ss_s[32];

    const int tid = threadIdx.x;
    const int n0  = blockIdx.x * 32;

    for (int i = tid; i < LL*BB*DD/4; i += 256)
        ((float4*)gb_s)[i] = ((const float4*)g_gb)[i];
    for (int i = tid; i < 32*12; i += 256) {
        int n = i / 12, l = i - n*12;
        int gn = n0 + n;
        sl_s[n][l] = (gn < NN) ? g_selL[(size_t)gn*12 + l] : 0.0f;
    }
    if (tid < 32) {
        int gn = n0 + tid;
        px_s[tid] = (gn < NN) ? g_px[gn] : 0.0f;
        py_s[tid] = (gn < NN) ? g_py[gn] : 0.0f;
        ss_s[tid] = (gn < NN) ? g_ss[gn] : 0.0f;
    }
    __syncthreads();

    const int warp = tid >> 5;
    const int lane = tid & 31;

    for (int i = 0; i < 4; i++) {
        int n  = warp * 4 + i;
        int gn = n0 + n;
        if (gn >= NN) continue;   // warp-uniform

        float px = px_s[n], py = py_s[n], ss = ss_s[n];
        float x0f = floorf(px), y0f = floorf(py);
        int   x0  = (int)x0f,   y0  = (int)y0f;
        float wx1 = px - x0f,   wy1 = py - y0f;
        float wx0 = 1.0f - wx1, wy0 = 1.0f - wy1;
        int x1 = x0 + 1, y1 = y0 + 1;
        bool vx0 = (x0 >= 0) & (x0 < WWW);
        bool vx1 = (x1 >= 0) & (x1 < WWW);
        bool vy0 = (y0 >= 0) & (y0 < HHH);
        bool vy1 = (y1 >= 0) & (y1 < HHH);
        int cx0 = min(max(x0, 0), WWW-1), cx1 = min(max(x1, 0), WWW-1);
        int cy0 = min(max(y0, 0), HHH-1), cy1 = min(max(y1, 0), HHH-1);

        float cw[4];
        int   cs[4];
        cw[0] = (vx0 && vy0) ? wx0*wy0 : 0.0f;  cs[0] = cy0*WWW + cx0;
        cw[1] = (vx1 && vy0) ? wx1*wy0 : 0.0f;  cs[1] = cy0*WWW + cx1;
        cw[2] = (vx0 && vy1) ? wx0*wy1 : 0.0f;  cs[2] = cy1*WWW + cx0;
        cw[3] = (vx1 && vy1) ? wx1*wy1 : 0.0f;  cs[3] = cy1*WWW + cx1;

        float4 ow4 = *(const float4*)&ow[(size_t)gn*DD + lane*4];

        float4 accL[4], accG[4];
        #pragma unroll
        for (int b = 0; b < 4; b++) {
            accL[b] = make_float4(0,0,0,0);
            accG[b] = make_float4(0,0,0,0);
        }

        for (int l = 0; l < LL; l++) {
            float wl = sl_s[n][l];
            #pragma unroll
            for (int p = 0; p < 4; p++) {
                float wp = wl * cw[p];
                if (wp != 0.0f) {
                    const float* fp = g_feat + (((size_t)l*HWK + cs[p])*BB)*DD + lane*4;
                    #pragma unroll
                    for (int b = 0; b < 4; b++) {
                        float4 f = *(const float4*)(fp + (size_t)b*DD);
                        accL[b].x += wp*f.x; accL[b].y += wp*f.y;
                        accL[b].z += wp*f.z; accL[b].w += wp*f.w;
                    }
                }
            }
            #pragma unroll
            for (int b = 0; b < 4; b++) {
                float4 g = *(const float4*)&gb_s[(size_t)(l*BB + b)*DD + lane*4];
                accG[b].x += wl*g.x; accG[b].y += wl*g.y;
                accG[b].z += wl*g.z; accG[b].w += wl*g.w;
            }
        }

        #pragma unroll
        for (int b = 0; b < 4; b++) {
            float dl = accL[b].x*ow4.x + accL[b].y*ow4.y + accL[b].z*ow4.z + accL[b].w*ow4.w;
            float dg = accG[b].x*ow4.x + accG[b].y*ow4.y + accG[b].z*ow4.z + accG[b].w*ow4.w;
            float s  = (1.0f - ss)*dl + ss*dg;
            #pragma unroll
            for (int o = 16; o; o >>= 1) s += __shfl_xor_sync(0xffffffffu, s, o);
            if (lane == 0) out[(size_t)b*NN + gn] = s * (1.0f/DD) + ob[gn];
        }
    }
}

// ---------------- reg scalar: deterministic fixed-order reduce ----------------
__global__ void reg_kernel(float* __restrict__ out, int has_reg) {
    if (threadIdx.x == 0 && blockIdx.x == 0) {
        float es = 0.0f, qs = 0.0f;
        for (int i = 0; i < NBLK_SEL; i++) { es += g_part[2*i]; qs += g_part[2*i+1]; }
        float entropy = es / (float)NN;
        float reg = entropy / logf(12.0f) + qs / (float)NN;
        if (has_reg) out[BB*NN] = reg;
    }
}

// ---------------- launch ----------------
extern "C" void kernel_launch(void* const* d_in, const int* in_sizes, int n_in,
                              void* d_out, int out_size) {
    const float* lt     = (const float*)d_in[0];   // local_tokens  [12,4,768,16,16]
    const float* gt     = (const float*)d_in[1];   // global_tokens [12,4,768]
    const float* coords = (const float*)d_in[2];   // [30000,3]
    const float* conv_w = (const float*)d_in[3];   // [12,128,768]
    const float* glob_w = (const float*)d_in[4];   // [12,128,768]
    const float* W1     = (const float*)d_in[5];   // [3,192,128]
    const float* b1     = (const float*)d_in[6];   // [3,128]
    const float* W2     = (const float*)d_in[7];   // [3,128,128]
    const float* b2     = (const float*)d_in[8];   // [3,128]
    const float* W3s    = (const float*)d_in[9];   // [128,2]
    const float* W3l    = (const float*)d_in[10];  // [128,12]
    const float* W3c    = (const float*)d_in[11];  // [128,1]
    const float* ow     = (const float*)d_in[12];  // [30000,128]
    const float* ob     = (const float*)d_in[13];  // [30000]
    float* out = (float*)d_out;

    transpose_cw_kernel<<<dim3(4, 24, 12), dim3(32, 8)>>>(conv_w);
    selector_kernel<<<NBLK_SEL, 256>>>(coords, W1, b1, W2, b2, W3s, W3l, W3c);
    feat_kernel<<<dim3(8, 48), 256>>>(lt);
    gb_kernel<<<768, 256>>>(gt, glob_w);
    final_kernel<<<NBLK_SEL, 256>>>(ow, ob, out);
    reg_kernel<<<1, 32>>>(out, (out_size > BB*NN) ? 1 : 0);
}

// round 3
// speedup vs baseline: 1.2746x; 1.2746x over previous
#include <cuda_runtime.h>
#include <cstdint>
#include <math.h>

#define LL   12
#define BB   4
#define CC   768
#define HHH  16
#define WWW  16
#define NN   30000
#define DD   128
#define PEK  192
#define HWK  256
#define NPB  64                    // points per selector block
#define NBLK_SEL 469               // ceil(30000/64)
#define NBLK_FIN 938               // ceil(30000/32)

// shared strides chosen for conflict-free mma fragment loads
#define PE_S 196                   // ≡ 4 (mod 32)
#define H_S  132                   // ≡ 4 (mod 32)
#define W_S  136                   // ≡ 8 (mod 32)

#define SEL_SMEM_FLOATS (NPB*PE_S + NPB*H_S + 64*W_S + NPB*12 + NPB + NPB)
#define SEL_SMEM_BYTES  (SEL_SMEM_FLOATS * 4)

// ---------------- scratch (no allocations allowed) ----------------
__device__ float g_cwT [LL*CC*DD];        // conv_w transposed: [l][c][d]
__device__ float g_feat[LL*HWK*BB*DD];    // [l][site][b][d]
__device__ float g_gb  [LL*BB*DD];        // [l][b][d]
__device__ float g_selL[NN*LL];           // softmax layer weights
__device__ float g_px  [NN];
__device__ float g_py  [NN];
__device__ float g_ss  [NN];
__device__ float g_part[2*NBLK_SEL];      // per-block (entropy_sum, scale_sq_sum)

__device__ __forceinline__ float gelu_exact(float x) {
    return 0.5f * x * (1.0f + erff(x * 0.7071067811865476f));
}

__device__ __forceinline__ unsigned int to_tf32(float x) {
    unsigned int u;
    asm("cvt.rna.tf32.f32 %0, %1;" : "=r"(u) : "f"(x));
    return u;
}

__device__ __forceinline__ void mma_tf32(float c[4], unsigned int a0, unsigned int a1,
                                         unsigned int a2, unsigned int a3,
                                         unsigned int b0, unsigned int b1) {
    asm volatile(
        "mma.sync.aligned.m16n8k8.row.col.f32.tf32.tf32.f32 "
        "{%0,%1,%2,%3},{%4,%5,%6,%7},{%8,%9},{%0,%1,%2,%3};\n"
        : "+f"(c[0]), "+f"(c[1]), "+f"(c[2]), "+f"(c[3])
        : "r"(a0), "r"(a1), "r"(a2), "r"(a3), "r"(b0), "r"(b1));
}

// ---------------- conv_w transpose: [l][d][c] -> [l][c][d] ----------------
__global__ void transpose_cw_kernel(const float* __restrict__ cw) {
    __shared__ float t[32][33];
    const int l  = blockIdx.z;
    const int d0 = blockIdx.x * 32;
    const int c0 = blockIdx.y * 32;
    for (int i = threadIdx.y; i < 32; i += 8)
        t[i][threadIdx.x] = cw[((size_t)l*DD + d0 + i)*CC + c0 + threadIdx.x];
    __syncthreads();
    for (int i = threadIdx.y; i < 32; i += 8)
        g_cwT[((size_t)l*CC + c0 + i)*DD + d0 + threadIdx.x] = t[threadIdx.x][i];
}

// ---------------- selector v2: tf32 tensor-core MLP ----------------
// 64 points/block, 8 warps; warp (wid>>1, wid&1) owns a 16n x 64j tile.
__device__ __forceinline__ void gemm_layer_tf32(
    const float* __restrict__ A, int As, int K,
    const float* __restrict__ Wg,          // [K][128] row-major global
    float* w_s, float cacc[8][4],
    int tid, int nw, int jw, int r, int c)
{
    for (int kc = 0; kc < K; kc += 64) {
        __syncthreads();   // previous chunk's mma done before overwrite
        // stage 64x128 weight chunk, tf32-rounded, STS.128
        for (int i = tid; i < 64*32; i += 256) {
            int row = i >> 5, c4 = (i & 31) * 4;
            float4 v = *(const float4*)(Wg + (size_t)(kc + row)*DD + c4);
            uint4 t;
            t.x = to_tf32(v.x); t.y = to_tf32(v.y);
            t.z = to_tf32(v.z); t.w = to_tf32(v.w);
            *(uint4*)&w_s[row*W_S + c4] = t;
        }
        __syncthreads();
        #pragma unroll
        for (int ks = 0; ks < 8; ks++) {
            int kk = ks * 8;
            unsigned int a0 = __float_as_uint(A[(nw + r    )*As + kc + kk + c    ]);
            unsigned int a1 = __float_as_uint(A[(nw + r + 8)*As + kc + kk + c    ]);
            unsigned int a2 = __float_as_uint(A[(nw + r    )*As + kc + kk + c + 4]);
            unsigned int a3 = __float_as_uint(A[(nw + r + 8)*As + kc + kk + c + 4]);
            #pragma unroll
            for (int jt = 0; jt < 8; jt++) {
                unsigned int b0 = __float_as_uint(w_s[(kk + c    )*W_S + jw + jt*8 + r]);
                unsigned int b1 = __float_as_uint(w_s[(kk + c + 4)*W_S + jw + jt*8 + r]);
                mma_tf32(cacc[jt], a0, a1, a2, a3, b0, b1);
            }
        }
    }
}

__global__ __launch_bounds__(256) void selector2_kernel(
    const float* __restrict__ coords,
    const float* __restrict__ W1all, const float* __restrict__ b1all,
    const float* __restrict__ W2all, const float* __restrict__ b2all,
    const float* __restrict__ W3s,   const float* __restrict__ W3l,
    const float* __restrict__ W3c)
{
    extern __shared__ float smem[];
    float* pe_s  = smem;                      // [64][PE_S]
    float* h_s   = pe_s + NPB*PE_S;           // [64][H_S]
    float* w_s   = h_s  + NPB*H_S;            // [64][W_S]
    float* outs  = w_s  + 64*W_S;             // [64][12]
    float* ent_s = outs + NPB*12;             // [64]
    float* sq_s  = ent_s + NPB;               // [64]

    const int tid  = threadIdx.x;
    const int n0   = blockIdx.x * NPB;
    const int wid  = tid >> 5;
    const int lane = tid & 31;
    const int r    = lane >> 2;
    const int c    = lane & 3;
    const int nw   = (wid >> 1) * 16;
    const int jw   = (wid & 1) * 64;

    // positional encoding (accurate sinf/cosf, tf32-rounded storage)
    for (int idx = tid; idx < NPB*PEK; idx += 256) {
        int n = idx / PEK, k = idx - n*PEK;
        int cc = k >> 6, rr = k & 63, f = rr & 31;
        int gn = n0 + n;
        float x = (gn < NN) ? coords[gn*3 + cc] : 0.0f;
        float freq = exp2f((8.0f/31.0f) * (float)f) * 3.14159265358979323846f;
        float ang = x * freq;
        float val = (rr < 32) ? sinf(ang) : cosf(ang);
        pe_s[n*PE_S + k] = __uint_as_float(to_tf32(val));
    }
    __syncthreads();

    for (int head = 0; head < 3; head++) {
        const float* w1 = W1all + (size_t)head*PEK*DD;
        const float* w2 = W2all + (size_t)head*DD*DD;
        float cacc[8][4];

        // ---- layer 1: h = gelu(pe @ W1 + b1), tf32 stored
        #pragma unroll
        for (int jt = 0; jt < 8; jt++)
            #pragma unroll
            for (int i = 0; i < 4; i++) cacc[jt][i] = 0.0f;
        gemm_layer_tf32(pe_s, PE_S, PEK, w1, w_s, cacc, tid, nw, jw, r, c);
        #pragma unroll
        for (int jt = 0; jt < 8; jt++) {
            int col = jw + jt*8 + 2*c;
            float bz0 = b1all[head*DD + col], bz1 = b1all[head*DD + col + 1];
            h_s[(nw + r    )*H_S + col    ] = __uint_as_float(to_tf32(gelu_exact(cacc[jt][0] + bz0)));
            h_s[(nw + r    )*H_S + col + 1] = __uint_as_float(to_tf32(gelu_exact(cacc[jt][1] + bz1)));
            h_s[(nw + r + 8)*H_S + col    ] = __uint_as_float(to_tf32(gelu_exact(cacc[jt][2] + bz0)));
            h_s[(nw + r + 8)*H_S + col + 1] = __uint_as_float(to_tf32(gelu_exact(cacc[jt][3] + bz1)));
        }
        // ---- layer 2: h2 = gelu(h @ W2 + b2), fp32 stored (feeds scalar W3)
        #pragma unroll
        for (int jt = 0; jt < 8; jt++)
            #pragma unroll
            for (int i = 0; i < 4; i++) cacc[jt][i] = 0.0f;
        gemm_layer_tf32(h_s, H_S, DD, w2, w_s, cacc, tid, nw, jw, r, c);
        __syncthreads();   // all mma reads of h_s done before overwrite
        #pragma unroll
        for (int jt = 0; jt < 8; jt++) {
            int col = jw + jt*8 + 2*c;
            float bz0 = b2all[head*DD + col], bz1 = b2all[head*DD + col + 1];
            h_s[(nw + r    )*H_S + col    ] = gelu_exact(cacc[jt][0] + bz0);
            h_s[(nw + r    )*H_S + col + 1] = gelu_exact(cacc[jt][1] + bz1);
            h_s[(nw + r + 8)*H_S + col    ] = gelu_exact(cacc[jt][2] + bz0);
            h_s[(nw + r + 8)*H_S + col + 1] = gelu_exact(cacc[jt][3] + bz1);
        }
        __syncthreads();

        // ---- W3 + activation (fp32 scalar)
        if (head == 0) {            // space -> tanh -> pixel coords
            if (tid < 128) {
                int n = tid >> 1, j = tid & 1;
                float a = 0.0f;
                for (int k = 0; k < DD; k++) a += h_s[n*H_S + k] * W3s[k*2 + j];
                outs[n*12 + j] = tanhf(a);
            }
            __syncthreads();
            if (tid < NPB) {
                int gn = n0 + tid;
                if (gn < NN) {
                    g_px[gn] = (outs[tid*12 + 0] + 1.0f) * (WWW * 0.5f) - 0.5f;
                    g_py[gn] = (outs[tid*12 + 1] + 1.0f) * (HHH * 0.5f) - 0.5f;
                }
            }
            __syncthreads();
        } else if (head == 1) {     // layer -> softmax + entropy
            for (int idx = tid; idx < NPB*12; idx += 256) {
                int n = idx / 12, j = idx - n*12;
                float a = 0.0f;
                for (int k = 0; k < DD; k++) a += h_s[n*H_S + k] * W3l[k*12 + j];
                outs[n*12 + j] = a;
            }
            __syncthreads();
            if (tid < NPB) {
                int gn = n0 + tid;
                float m = outs[tid*12];
                #pragma unroll
                for (int l = 1; l < 12; l++) m = fmaxf(m, outs[tid*12 + l]);
                float s = 0.0f, e[12];
                #pragma unroll
                for (int l = 0; l < 12; l++) { e[l] = expf(outs[tid*12 + l] - m); s += e[l]; }
                float inv = 1.0f / s;
                float en = 0.0f;
                #pragma unroll
                for (int l = 0; l < 12; l++) {
                    float p = e[l] * inv;
                    if (gn < NN) g_selL[(size_t)gn*12 + l] = p;
                    en += p * logf(p + 1e-8f);
                }
                ent_s[tid] = (gn < NN) ? en : 0.0f;
            }
            __syncthreads();
        } else {                    // scale -> sigmoid
            if (tid < NPB) {
                int gn = n0 + tid;
                float a = 0.0f;
                for (int k = 0; k < DD; k++) a += h_s[tid*H_S + k] * W3c[k];
                float s = 1.0f / (1.0f + expf(-a));
                if (gn < NN) g_ss[gn] = s;
                sq_s[tid] = (gn < NN) ? (s - 0.5f) * (s - 0.5f) : 0.0f;
            }
            __syncthreads();
        }
    }

    if (tid == 0) {
        float es = 0.0f, qs = 0.0f;
        for (int i = 0; i < NPB; i++) { es += ent_s[i]; qs += sq_s[i]; }
        g_part[blockIdx.x*2 + 0] = es;
        g_part[blockIdx.x*2 + 1] = qs;
    }
}

// ---------------- feat GEMM ----------------
__global__ __launch_bounds__(256) void feat_kernel(const float* __restrict__ lt) {
    __shared__ float a_s[8][36];
    __shared__ float w_s[8][128];
    const int lb  = blockIdx.y;
    const int l   = lb >> 2;
    const int hw0 = blockIdx.x * 32;
    const int tid = threadIdx.x;
    const int td  = tid & 31;
    const int thw = tid >> 5;
    const int b   = lb & 3;

    float acc[4][4];
    #pragma unroll
    for (int i = 0; i < 4; i++)
        #pragma unroll
        for (int j = 0; j < 4; j++) acc[i][j] = 0.0f;

    const float* base = lt + (size_t)lb * CC * HWK;

    for (int c0 = 0; c0 < CC; c0 += 8) {
        {
            int kk = tid >> 5, s = tid & 31;
            a_s[kk][s] = base[(size_t)(c0+kk)*HWK + hw0 + s];
            *(float4*)&w_s[kk][s*4] =
                *(const float4*)&g_cwT[((size_t)l*CC + c0 + kk)*DD + s*4];
        }
        __syncthreads();
        #pragma unroll
        for (int kk = 0; kk < 8; kk++) {
            float4 w = *(float4*)&w_s[kk][td*4];
            #pragma unroll
            for (int i = 0; i < 4; i++) {
                float p = a_s[kk][thw*4 + i];
                acc[i][0] += p*w.x; acc[i][1] += p*w.y;
                acc[i][2] += p*w.z; acc[i][3] += p*w.w;
            }
        }
        __syncthreads();
    }
    #pragma unroll
    for (int i = 0; i < 4; i++) {
        int site = hw0 + thw*4 + i;
        float4 v = make_float4(acc[i][0], acc[i][1], acc[i][2], acc[i][3]);
        *(float4*)&g_feat[(((size_t)l*HWK + site)*BB + b)*DD + td*4] = v;
    }
}

// ---------------- global bottleneck ----------------
__global__ __launch_bounds__(256) void gb_kernel(const float* __restrict__ gt,
                                                 const float* __restrict__ gw) {
    int wid  = (blockIdx.x * 256 + threadIdx.x) >> 5;
    int lane = threadIdx.x & 31;
    if (wid >= LL*BB*DD) return;
    int l = wid / (BB*DD);
    int rr = wid - l*(BB*DD);
    int b = rr / DD;
    int d = rr - b*DD;
    const float* a = gt + (size_t)(l*BB + b)*CC;
    const float* w = gw + (size_t)(l*DD + d)*CC;
    float s = 0.0f;
    for (int cc = lane; cc < CC; cc += 32) s += a[cc] * w[cc];
    #pragma unroll
    for (int o = 16; o; o >>= 1) s += __shfl_xor_sync(0xffffffffu, s, o);
    if (lane == 0) g_gb[(size_t)(l*BB + b)*DD + d] = s;
}

// ---------------- final ----------------
__global__ __launch_bounds__(256) void final_kernel(const float* __restrict__ ow,
                                                    const float* __restrict__ ob,
                                                    float* __restrict__ out) {
    __shared__ float gb_s[LL*BB*DD];
    __shared__ float sl_s[32][12];
    __shared__ float px_s[32], py_s[32], ss_s[32];

    const int tid = threadIdx.x;
    const int n0  = blockIdx.x * 32;

    for (int i = tid; i < LL*BB*DD/4; i += 256)
        ((float4*)gb_s)[i] = ((const float4*)g_gb)[i];
    for (int i = tid; i < 32*12; i += 256) {
        int n = i / 12, l = i - n*12;
        int gn = n0 + n;
        sl_s[n][l] = (gn < NN) ? g_selL[(size_t)gn*12 + l] : 0.0f;
    }
    if (tid < 32) {
        int gn = n0 + tid;
        px_s[tid] = (gn < NN) ? g_px[gn] : 0.0f;
        py_s[tid] = (gn < NN) ? g_py[gn] : 0.0f;
        ss_s[tid] = (gn < NN) ? g_ss[gn] : 0.0f;
    }
    __syncthreads();

    const int warp = tid >> 5;
    const int lane = tid & 31;

    for (int i = 0; i < 4; i++) {
        int n  = warp * 4 + i;
        int gn = n0 + n;
        if (gn >= NN) continue;

        float px = px_s[n], py = py_s[n], ss = ss_s[n];
        float x0f = floorf(px), y0f = floorf(py);
        int   x0  = (int)x0f,   y0  = (int)y0f;
        float wx1 = px - x0f,   wy1 = py - y0f;
        float wx0 = 1.0f - wx1, wy0 = 1.0f - wy1;
        int x1 = x0 + 1, y1 = y0 + 1;
        bool vx0 = (x0 >= 0) & (x0 < WWW);
        bool vx1 = (x1 >= 0) & (x1 < WWW);
        bool vy0 = (y0 >= 0) & (y0 < HHH);
        bool vy1 = (y1 >= 0) & (y1 < HHH);
        int cx0 = min(max(x0, 0), WWW-1), cx1 = min(max(x1, 0), WWW-1);
        int cy0 = min(max(y0, 0), HHH-1), cy1 = min(max(y1, 0), HHH-1);

        float cw[4];
        int   cs[4];
        cw[0] = (vx0 && vy0) ? wx0*wy0 : 0.0f;  cs[0] = cy0*WWW + cx0;
        cw[1] = (vx1 && vy0) ? wx1*wy0 : 0.0f;  cs[1] = cy0*WWW + cx1;
        cw[2] = (vx0 && vy1) ? wx0*wy1 : 0.0f;  cs[2] = cy1*WWW + cx0;
        cw[3] = (vx1 && vy1) ? wx1*wy1 : 0.0f;  cs[3] = cy1*WWW + cx1;

        float4 ow4 = *(const float4*)&ow[(size_t)gn*DD + lane*4];

        float4 accL[4], accG[4];
        #pragma unroll
        for (int b = 0; b < 4; b++) {
            accL[b] = make_float4(0,0,0,0);
            accG[b] = make_float4(0,0,0,0);
        }

        for (int l = 0; l < LL; l++) {
            float wl = sl_s[n][l];
            #pragma unroll
            for (int p = 0; p < 4; p++) {
                float wp = wl * cw[p];
                if (wp != 0.0f) {
                    const float* fp = g_feat + (((size_t)l*HWK + cs[p])*BB)*DD + lane*4;
                    #pragma unroll
                    for (int b = 0; b < 4; b++) {
                        float4 f = *(const float4*)(fp + (size_t)b*DD);
                        accL[b].x += wp*f.x; accL[b].y += wp*f.y;
                        accL[b].z += wp*f.z; accL[b].w += wp*f.w;
                    }
                }
            }
            #pragma unroll
            for (int b = 0; b < 4; b++) {
                float4 g = *(const float4*)&gb_s[(size_t)(l*BB + b)*DD + lane*4];
                accG[b].x += wl*g.x; accG[b].y += wl*g.y;
                accG[b].z += wl*g.z; accG[b].w += wl*g.w;
            }
        }

        #pragma unroll
        for (int b = 0; b < 4; b++) {
            float dl = accL[b].x*ow4.x + accL[b].y*ow4.y + accL[b].z*ow4.z + accL[b].w*ow4.w;
            float dg = accG[b].x*ow4.x + accG[b].y*ow4.y + accG[b].z*ow4.z + accG[b].w*ow4.w;
            float s  = (1.0f - ss)*dl + ss*dg;
            #pragma unroll
            for (int o = 16; o; o >>= 1) s += __shfl_xor_sync(0xffffffffu, s, o);
            if (lane == 0) out[(size_t)b*NN + gn] = s * (1.0f/DD) + ob[gn];
        }
    }
}

// ---------------- reg scalar ----------------
__global__ void reg_kernel(float* __restrict__ out, int has_reg) {
    if (threadIdx.x == 0 && blockIdx.x == 0) {
        float es = 0.0f, qs = 0.0f;
        for (int i = 0; i < NBLK_SEL; i++) { es += g_part[2*i]; qs += g_part[2*i+1]; }
        float entropy = es / (float)NN;
        float reg = entropy / logf(12.0f) + qs / (float)NN;
        if (has_reg) out[BB*NN] = reg;
    }
}

// ---------------- launch ----------------
extern "C" void kernel_launch(void* const* d_in, const int* in_sizes, int n_in,
                              void* d_out, int out_size) {
    const float* lt     = (const float*)d_in[0];
    const float* gt     = (const float*)d_in[1];
    const float* coords = (const float*)d_in[2];
    const float* conv_w = (const float*)d_in[3];
    const float* glob_w = (const float*)d_in[4];
    const float* W1     = (const float*)d_in[5];
    const float* b1     = (const float*)d_in[6];
    const float* W2     = (const float*)d_in[7];
    const float* b2     = (const float*)d_in[8];
    const float* W3s    = (const float*)d_in[9];
    const float* W3l    = (const float*)d_in[10];
    const float* W3c    = (const float*)d_in[11];
    const float* ow     = (const float*)d_in[12];
    const float* ob     = (const float*)d_in[13];
    float* out = (float*)d_out;

    cudaFuncSetAttribute(selector2_kernel,
                         cudaFuncAttributeMaxDynamicSharedMemorySize, SEL_SMEM_BYTES);

    transpose_cw_kernel<<<dim3(4, 24, 12), dim3(32, 8)>>>(conv_w);
    selector2_kernel<<<NBLK_SEL, 256, SEL_SMEM_BYTES>>>(coords, W1, b1, W2, b2, W3s, W3l, W3c);
    feat_kernel<<<dim3(8, 48), 256>>>(lt);
    gb_kernel<<<768, 256>>>(gt, glob_w);
    final_kernel<<<NBLK_FIN, 256>>>(ow, ob, out);
    reg_kernel<<<1, 32>>>(out, (out_size > BB*NN) ? 1 : 0);
}